// round 15
// baseline (speedup 1.0000x reference)
#include <cuda_runtime.h>
#include <cuda_fp16.h>
#include <cstdint>

#define N_PAD   50048
#define DIM     256
#define NEG     0.2f
#define LN_EPS  1e-5f
#define THREADS 512

// SMEM: B 4 chunk-planes (128K) | A16 per-group (2 x 32K) | per-group buffers
#define B_CHUNK  32768
#define A16_OFF  131072
#define A16_GRP  32768
#define BUF_OFF  196608
#define BUF_GRP  5632          // 1408 floats
#define SMEM_BYTES (BUF_OFF + 2 * BUF_GRP)   // 207872

// ---------------- scratch ----------------
__device__ unsigned char g_mask[3 * N_PAD];
__device__ uint32_t g_wh[4 * 256 * 32];   // Wr fp16 chunk-major pairs

// ---------------- helpers ----------------
__device__ __forceinline__ uint32_t pack_f16(float a, float b) {
    __half2 h = __floats2half2_rn(a, b);
    return *reinterpret_cast<uint32_t*>(&h);
}
__device__ __forceinline__ uint32_t s2u(const void* p) {
    return (uint32_t)__cvta_generic_to_shared(p);
}
__device__ __forceinline__ uint32_t swz(uint32_t off) {
    return off ^ ((off >> 3) & 0x70);
}
__device__ __forceinline__ void cpasync16(uint32_t dst, const void* src) {
    asm volatile("cp.async.cg.shared.global [%0], [%1], 16;" :: "r"(dst), "l"(src));
}
__device__ __forceinline__ void cpcommit() { asm volatile("cp.async.commit_group;"); }
__device__ __forceinline__ void cpwait0()  { asm volatile("cp.async.wait_group 0;"); }
__device__ __forceinline__ void ldmx4(uint32_t r[4], uint32_t addr) {
    asm volatile("ldmatrix.sync.aligned.m8n8.x4.shared.b16 {%0,%1,%2,%3}, [%4];"
                 : "=r"(r[0]), "=r"(r[1]), "=r"(r[2]), "=r"(r[3]) : "r"(addr));
}
__device__ __forceinline__ void mma16816(float c[4], const uint32_t a[4],
                                         uint32_t b0, uint32_t b1) {
    asm("mma.sync.aligned.m16n8k16.row.col.f32.f16.f16.f32 "
        "{%0,%1,%2,%3}, {%4,%5,%6,%7}, {%8,%9}, {%0,%1,%2,%3};"
        : "+f"(c[0]), "+f"(c[1]), "+f"(c[2]), "+f"(c[3])
        : "r"(a[0]), "r"(a[1]), "r"(a[2]), "r"(a[3]), "r"(b0), "r"(b1));
}
__device__ __forceinline__ float head_w(float q, float kv, float n1) {
    float x1 = q + kv;
    float z1 = fmaxf(x1, NEG * x1);
    float z0 = fmaxf(q,  NEG * q);
    float m  = fmaxf(z1, z0);
    float e1 = expf(z1 - m);
    float e0 = expf(z0 - m);
    float f1 = n1 * e1;
    return f1 / (f1 + (4.0f - n1) * e0);
}
// group-local barrier: 8 warps / 256 threads, ids 1 and 2
#define GBAR(g) asm volatile("bar.sync %0, %1;" :: "r"((g) + 1), "r"(256) : "memory")

// ---------------- prep (validated R7/R8) ----------------
#define W_BLOCKS 16
__global__ void prep_kernel(const float* __restrict__ Wr,
                            const int* __restrict__ d0,
                            const int* __restrict__ d1,
                            const int* __restrict__ d2, int E4)
{
    int b = blockIdx.x;
    if (b < W_BLOCKS) {
        int t   = b * 256 + threadIdx.x;
        int nc  = t >> 4;
        int seg = t & 15;
        int kb  = seg * 16;
        uint32_t h[8];
        #pragma unroll
        for (int p = 0; p < 8; p++) {
            float x0 = Wr[(size_t)(kb + 2 * p)     * 256 + nc];
            float x1 = Wr[(size_t)(kb + 2 * p + 1) * 256 + nc];
            h[p] = pack_f16(x0, x1);
        }
        int c = seg >> 2;
        size_t base = ((size_t)(c * 256 + nc)) * 32 + (seg & 3) * 8;
        *(uint4*)&g_wh[base]     = make_uint4(h[0], h[1], h[2], h[3]);
        *(uint4*)&g_wh[base + 4] = make_uint4(h[4], h[5], h[6], h[7]);
        return;
    }
    b -= W_BLOCKS;
    int i = b * 256 + threadIdx.x;
    if (i >= E4) return;
    int4 a  = ((const int4*)d0)[i];
    int4 bb = ((const int4*)d1)[i];
    int4 cc = ((const int4*)d2)[i];
    if (!g_mask[a.x]) g_mask[a.x] = 1;
    if (!g_mask[a.y]) g_mask[a.y] = 1;
    if (!g_mask[a.z]) g_mask[a.z] = 1;
    if (!g_mask[a.w]) g_mask[a.w] = 1;
    if (!g_mask[N_PAD + bb.x]) g_mask[N_PAD + bb.x] = 1;
    if (!g_mask[N_PAD + bb.y]) g_mask[N_PAD + bb.y] = 1;
    if (!g_mask[N_PAD + bb.z]) g_mask[N_PAD + bb.z] = 1;
    if (!g_mask[N_PAD + bb.w]) g_mask[N_PAD + bb.w] = 1;
    if (!g_mask[2 * N_PAD + cc.x]) g_mask[2 * N_PAD + cc.x] = 1;
    if (!g_mask[2 * N_PAD + cc.y]) g_mask[2 * N_PAD + cc.y] = 1;
    if (!g_mask[2 * N_PAD + cc.z]) g_mask[2 * N_PAD + cc.z] = 1;
    if (!g_mask[2 * N_PAD + cc.w]) g_mask[2 * N_PAD + cc.w] = 1;
}

// ---------------- persistent dual-group GEMM + epilogue ----------------
// 512 threads = 2 groups x 8 warps. Group g handles tiles 2*blk+g, stride 2*grid.
// Warp tile 32x64 (2m x 4n per group); warp covers exactly one head (64 cols).
__global__ __launch_bounds__(THREADS, 1)
void gemm_epilogue(const float* __restrict__ feat,
                   const float* __restrict__ br,
                   const float* __restrict__ rel_q,
                   const float* __restrict__ rel_k,
                   const float* __restrict__ ln_g,
                   const float* __restrict__ ln_b,
                   float* __restrict__ out, int n)
{
    extern __shared__ char smem[];
    const uint32_t su = s2u(smem);
    const int tid  = threadIdx.x;
    const int wid  = tid >> 5;
    const int lane = tid & 31;
    const int g    = wid >> 3;       // group 0/1
    const int gwid = wid & 7;
    const int gtid = tid & 255;
    const int wm   = gwid & 1;       // rows wm*32..+31
    const int wn   = gwid >> 1;      // head / cols wn*64..+63

    // per-group buffers
    float* buf = (float*)(smem + BUF_OFF + g * BUF_GRP);
    float* pqb = buf;          // [64][4]
    float* pkb = buf + 256;    // [64][4]
    float* wb  = buf + 512;    // [64][4]
    float* s1b = buf + 768;    // [64][4]
    float* s2b = buf + 1024;   // [64][4]
    float* mub = buf + 1280;   // [64]
    float* rsb = buf + 1344;   // [64]

    // ---- load ALL of B once (whole CTA) ----
    {
        const int bn = tid >> 1;
        const int bj = (tid & 1) * 4;
        #pragma unroll
        for (int c = 0; c < 4; c++) {
            const uint32_t* bf = g_wh + (size_t)c * 8192 + (size_t)bn * 32 + bj * 4;
            const uint32_t dstb = su + (uint32_t)c * B_CHUNK;
            #pragma unroll
            for (int u = 0; u < 4; u++)
                cpasync16(dstb + swz((uint32_t)(bn * 128 + (bj + u) * 16)), bf + u * 4);
        }
        cpcommit();
    }

    // fragment address components
    const int l7  = lane & 7;
    const int q01 = (lane >> 3) & 1;
    const int q23 = lane >> 4;
    uint32_t arowb[2];
    #pragma unroll
    for (int mt = 0; mt < 2; mt++)
        arowb[mt] = (uint32_t)((wm * 32 + mt * 16 + q01 * 8 + l7) * 128);
    const uint32_t bg   = (uint32_t)((lane >> 3) * 16);
    const uint32_t brb0 = (uint32_t)((wn * 64 + l7) * 128);   // + nt*1024 + p*64 + bg

    // A staging: 256 threads, thread -> (row gtid>>2, chunk gtid&3), 64 floats
    const int arow = gtid >> 2;
    const int aseg = gtid & 3;
    char* aplane = smem + A16_OFF + g * A16_GRP + aseg * 8192;
    const uint32_t abase = (uint32_t)(arow * 128);
    const uint32_t agbase = su + A16_OFF + (uint32_t)g * A16_GRP;

    // epilogue lane mapping
    const int cq = (lane & 3) * 2;
    const int rg = lane >> 2;

    cpwait0();
    __syncthreads();     // B resident (single full-CTA barrier)

    const int ntiles = (n + 63) >> 6;   // 782
    const int stride = 2 * gridDim.x;

    for (int s = 2 * blockIdx.x + g; s < ntiles; s += stride) {
        const int row0 = s * 64;

        // ---- stage A16(s) ----
        {
            int gr = row0 + arow; if (gr >= n) gr = n - 1;
            const float4* af = (const float4*)(feat + (size_t)gr * 256 + aseg * 64);
            float4 v[16];
            #pragma unroll
            for (int i = 0; i < 16; i++) v[i] = af[i];
            #pragma unroll
            for (int j = 0; j < 8; j++) {
                uint4 h = make_uint4(pack_f16(v[2*j].x,   v[2*j].y),
                                     pack_f16(v[2*j].z,   v[2*j].w),
                                     pack_f16(v[2*j+1].x, v[2*j+1].y),
                                     pack_f16(v[2*j+1].z, v[2*j+1].w));
                *(uint4*)(aplane + swz(abase + j * 16)) = h;
            }
        }
        GBAR(g);   // B1: A16 ready

        // ---- compute: 4 chunks x 2 halves; acc[2][8][4] ----
        float acc[2][8][4];
        #pragma unroll
        for (int mt = 0; mt < 2; mt++)
            #pragma unroll
            for (int nt = 0; nt < 8; nt++)
                #pragma unroll
                for (int q = 0; q < 4; q++) acc[mt][nt][q] = 0.0f;

        #pragma unroll
        for (int c = 0; c < 4; c++) {
            const uint32_t sa = agbase + (uint32_t)c * 8192;
            const uint32_t sb = su + (uint32_t)c * B_CHUNK;
            #pragma unroll
            for (int p = 0; p < 2; p++) {
                uint32_t ah[2][2][4];
                #pragma unroll
                for (int mt = 0; mt < 2; mt++)
                    #pragma unroll
                    for (int kk = 0; kk < 2; kk++)
                        ldmx4(ah[mt][kk], sa + swz(arowb[mt] + (uint32_t)((p * 2 + kk) * 32 + q23 * 16)));
                #pragma unroll
                for (int np = 0; np < 4; np++) {
                    const int nt0 = 2 * np, nt1 = 2 * np + 1;
                    uint32_t bh0[4], bh1[4];
                    ldmx4(bh0, sb + swz(brb0 + (uint32_t)(nt0 * 1024 + p * 64) + bg));
                    ldmx4(bh1, sb + swz(brb0 + (uint32_t)(nt1 * 1024 + p * 64) + bg));
                    #pragma unroll
                    for (int kk = 0; kk < 2; kk++) {
                        mma16816(acc[0][nt0], ah[0][kk], bh0[2*kk], bh0[2*kk+1]);
                        mma16816(acc[1][nt0], ah[1][kk], bh0[2*kk], bh0[2*kk+1]);
                        mma16816(acc[0][nt1], ah[0][kk], bh1[2*kk], bh1[2*kk+1]);
                        mma16816(acc[1][nt1], ah[1][kk], bh1[2*kk], bh1[2*kk+1]);
                    }
                }
            }
        }

        // ---- phase 1: v = acc + br; head dot-partials; quad-reduce ----
        float pq[2][2] = {{0,0},{0,0}}, pk[2][2] = {{0,0},{0,0}};
        #pragma unroll
        for (int nt = 0; nt < 8; nt++) {
            int col = wn * 64 + nt * 8 + cq;
            float b0 = __ldg(&br[col]),    b1 = __ldg(&br[col + 1]);
            float r0 = __ldg(&rel_q[col]), r1 = __ldg(&rel_q[col + 1]);
            float k0 = __ldg(&rel_k[col]), k1 = __ldg(&rel_k[col + 1]);
            #pragma unroll
            for (int mt = 0; mt < 2; mt++) {
                float v0 = acc[mt][nt][0] + b0;
                float v1 = acc[mt][nt][1] + b1;
                float v2 = acc[mt][nt][2] + b0;
                float v3 = acc[mt][nt][3] + b1;
                acc[mt][nt][0] = v0; acc[mt][nt][1] = v1;
                acc[mt][nt][2] = v2; acc[mt][nt][3] = v3;
                pq[mt][0] = fmaf(v0, r0, fmaf(v1, r1, pq[mt][0]));
                pq[mt][1] = fmaf(v2, r0, fmaf(v3, r1, pq[mt][1]));
                pk[mt][0] = fmaf(v0, k0, fmaf(v1, k1, pk[mt][0]));
                pk[mt][1] = fmaf(v2, k0, fmaf(v3, k1, pk[mt][1]));
            }
        }
        #pragma unroll
        for (int o = 1; o <= 2; o <<= 1)
            #pragma unroll
            for (int mt = 0; mt < 2; mt++)
                #pragma unroll
                for (int hf = 0; hf < 2; hf++) {
                    pq[mt][hf] += __shfl_xor_sync(0xffffffffu, pq[mt][hf], o);
                    pk[mt][hf] += __shfl_xor_sync(0xffffffffu, pk[mt][hf], o);
                }
        if ((lane & 3) == 0) {
            #pragma unroll
            for (int mt = 0; mt < 2; mt++)
                #pragma unroll
                for (int hf = 0; hf < 2; hf++) {
                    int rl = wm * 32 + mt * 16 + rg + hf * 8;
                    pqb[rl * 4 + wn] = pq[mt][hf];   // single writer per (row, head)
                    pkb[rl * 4 + wn] = pk[mt][hf];
                }
        }
        GBAR(g);   // B2

        // ---- phase 2: w per (row, head): 256 threads ----
        {
            int r = gtid >> 2, h = gtid & 3;
            float q  = pqb[r * 4 + h];
            float kv = pkb[r * 4 + h];
            int grow = row0 + r;
            float n1 = 1.0f + (float)g_mask[grow] + (float)g_mask[N_PAD + grow]
                            + (float)g_mask[2 * N_PAD + grow];
            wb[r * 4 + h] = head_w(q, kv, n1);
        }
        GBAR(g);   // B3

        // ---- phase 3: o = relu(v*w); LN partials; quad-reduce ----
        float s1[2][2] = {{0,0},{0,0}}, s2[2][2] = {{0,0},{0,0}};
        #pragma unroll
        for (int mt = 0; mt < 2; mt++) {
            int rl0 = wm * 32 + mt * 16 + rg;
            float w0 = wb[rl0 * 4 + wn];
            float w1 = wb[(rl0 + 8) * 4 + wn];
            #pragma unroll
            for (int nt = 0; nt < 8; nt++) {
                float o0 = fmaxf(acc[mt][nt][0] * w0, 0.f);
                float o1 = fmaxf(acc[mt][nt][1] * w0, 0.f);
                float o2 = fmaxf(acc[mt][nt][2] * w1, 0.f);
                float o3 = fmaxf(acc[mt][nt][3] * w1, 0.f);
                acc[mt][nt][0] = o0; acc[mt][nt][1] = o1;
                acc[mt][nt][2] = o2; acc[mt][nt][3] = o3;
                s1[mt][0] += o0 + o1;
                s1[mt][1] += o2 + o3;
                s2[mt][0] = fmaf(o0, o0, fmaf(o1, o1, s2[mt][0]));
                s2[mt][1] = fmaf(o2, o2, fmaf(o3, o3, s2[mt][1]));
            }
        }
        #pragma unroll
        for (int o = 1; o <= 2; o <<= 1)
            #pragma unroll
            for (int mt = 0; mt < 2; mt++)
                #pragma unroll
                for (int hf = 0; hf < 2; hf++) {
                    s1[mt][hf] += __shfl_xor_sync(0xffffffffu, s1[mt][hf], o);
                    s2[mt][hf] += __shfl_xor_sync(0xffffffffu, s2[mt][hf], o);
                }
        if ((lane & 3) == 0) {
            #pragma unroll
            for (int mt = 0; mt < 2; mt++)
                #pragma unroll
                for (int hf = 0; hf < 2; hf++) {
                    int rl = wm * 32 + mt * 16 + rg + hf * 8;
                    s1b[rl * 4 + wn] = s1[mt][hf];
                    s2b[rl * 4 + wn] = s2[mt][hf];
                }
        }
        GBAR(g);   // B4

        // ---- phase 4: mu / rsqrt per row (64 threads of group) ----
        if (gtid < 64) {
            float a = s1b[gtid * 4] + s1b[gtid * 4 + 1] + s1b[gtid * 4 + 2] + s1b[gtid * 4 + 3];
            float b2 = s2b[gtid * 4] + s2b[gtid * 4 + 1] + s2b[gtid * 4 + 2] + s2b[gtid * 4 + 3];
            float mu  = a * (1.0f / 256.0f);
            float var = b2 * (1.0f / 256.0f) - mu * mu;
            mub[gtid] = mu;
            rsb[gtid] = rsqrtf(var + LN_EPS);
        }
        GBAR(g);   // B5

        // ---- phase 5: normalize + store ----
        #pragma unroll
        for (int nt = 0; nt < 8; nt++) {
            int col = wn * 64 + nt * 8 + cq;
            float g0 = __ldg(&ln_g[col]), g1 = __ldg(&ln_g[col + 1]);
            float b0 = __ldg(&ln_b[col]), b1 = __ldg(&ln_b[col + 1]);
            #pragma unroll
            for (int mt = 0; mt < 2; mt++)
                #pragma unroll
                for (int hf = 0; hf < 2; hf++) {
                    int rl = wm * 32 + mt * 16 + rg + hf * 8;
                    int grow = row0 + rl;
                    if (grow >= n) continue;
                    float mu = mub[rl];
                    float rs = rsb[rl];
                    float2 st;
                    st.x = (acc[mt][nt][hf * 2]     - mu) * rs * g0 + b0;
                    st.y = (acc[mt][nt][hf * 2 + 1] - mu) * rs * g1 + b1;
                    *(float2*)&out[(size_t)grow * 256 + col] = st;
                }
        }
    }
}

// ---------------- launcher ----------------
extern "C" void kernel_launch(void* const* d_in, const int* in_sizes, int n_in,
                              void* d_out, int out_size)
{
    const float* feat  = (const float*)d_in[0];
    const float* Wr    = (const float*)d_in[3];
    const float* br    = (const float*)d_in[4];
    const float* rel_q = (const float*)d_in[7];
    const float* rel_k = (const float*)d_in[8];
    const float* ln_g  = (const float*)d_in[9];
    const float* ln_b  = (const float*)d_in[10];
    const int*   dst0  = (const int*)d_in[12];
    const int*   dst1  = (const int*)d_in[14];
    const int*   dst2  = (const int*)d_in[16];

    int n  = in_sizes[0] / DIM;   // 50000
    int E  = in_sizes[12];        // 400000
    int E4 = E / 4;

    static bool attr_set = false;
    if (!attr_set) {
        cudaFuncSetAttribute(gemm_epilogue,
                             cudaFuncAttributeMaxDynamicSharedMemorySize, SMEM_BYTES);
        cudaFuncSetAttribute(gemm_epilogue,
                             cudaFuncAttributePreferredSharedMemoryCarveout, 100);
        attr_set = true;
    }

    int scatter_blocks = (E4 + 255) / 256;
    prep_kernel<<<W_BLOCKS + scatter_blocks, 256>>>(Wr, dst0, dst1, dst2, E4);

    gemm_epilogue<<<148, THREADS, SMEM_BYTES>>>(
        feat, br, rel_q, rel_k, ln_g, ln_b, (float*)d_out, n);
}